// round 1
// baseline (speedup 1.0000x reference)
#include <cuda_runtime.h>

// Pull_37091337568590: 2D linear-interp warp with wrap (circulant) boundary.
// x:   [B=8, C=16, H=512, W=512] f32
// phi: [B=8, 2,    H=512, W=512] f32  (channel 0 = dy, channel 1 = dx)
// out: [B=8, C=16, H=512, W=512] f32
//
// One thread per (b, h, w) pixel; coordinates/weights computed once and
// reused across all 16 channels. H and W are powers of two, so wrap-mod
// is a bitwise AND (correct for negative ints in two's complement).

#define PB 8
#define PC 16
#define PH 512
#define PW 512
#define PHW (PH * PW)

__global__ __launch_bounds__(256)
void pull_wrap_kernel(const float* __restrict__ x,
                      const float* __restrict__ phi,
                      float* __restrict__ out)
{
    int idx = blockIdx.x * blockDim.x + threadIdx.x;
    // total = B*H*W = 2,097,152; grid sized exactly, no bounds check needed,
    // but keep a cheap guard for safety.
    if (idx >= PB * PHW) return;

    int b = idx >> 18;          // / (512*512)
    int p = idx & (PHW - 1);    // pixel within image plane
    int h = p >> 9;             // / 512
    int w = p & (PW - 1);

    const float* phib = phi + (size_t)b * 2 * PHW;
    float cy = phib[p]        + (float)h;   // absolute sample y
    float cx = phib[PHW + p]  + (float)w;   // absolute sample x

    float y0f = floorf(cy);
    float x0f = floorf(cx);
    float wy = cy - y0f;
    float wx = cx - x0f;

    int y0 = ((int)y0f) & (PH - 1);
    int x0 = ((int)x0f) & (PW - 1);
    int y1 = (y0 + 1) & (PH - 1);
    int x1 = (x0 + 1) & (PW - 1);

    int o00 = y0 * PW + x0;
    int o01 = y0 * PW + x1;
    int o10 = y1 * PW + x0;
    int o11 = y1 * PW + x1;

    float w00 = (1.0f - wy) * (1.0f - wx);
    float w01 = (1.0f - wy) * wx;
    float w10 = wy * (1.0f - wx);
    float w11 = wy * wx;

    const float* xb = x + (size_t)b * PC * PHW;
    float* ob = out + (size_t)b * PC * PHW + p;

#pragma unroll
    for (int c = 0; c < PC; c++) {
        const float* xc = xb + c * PHW;
        float v = __ldg(xc + o00) * w00
                + __ldg(xc + o01) * w01
                + __ldg(xc + o10) * w10
                + __ldg(xc + o11) * w11;
        ob[c * PHW] = v;
    }
}

extern "C" void kernel_launch(void* const* d_in, const int* in_sizes, int n_in,
                              void* d_out, int out_size)
{
    const float* x   = (const float*)d_in[0];
    const float* phi = (const float*)d_in[1];
    float* out = (float*)d_out;

    int total = PB * PHW;               // 2,097,152 threads
    int threads = 256;
    int blocks = (total + threads - 1) / threads;   // 8192
    pull_wrap_kernel<<<blocks, threads>>>(x, phi, out);
}